// round 4
// baseline (speedup 1.0000x reference)
#include <cuda_runtime.h>
#include <cuda_bf16.h>
#include <cstdint>

// ---------------- problem constants ----------------
#define NN 100000
#define EE 1600000
#define NG 512
#define D  100      // hidden dim
#define D2 200      // concat(u, r) width
#define K1 128      // input feature dim
#define SCAN_B ((NN + 255) / 256)   // 391 scan blocks

// ---------------- device scratch (static globals: allocation-free) ----------------
__device__ int   g_deg[NN];
__device__ int   g_cursor[NN];
__device__ int   g_off[NN];
__device__ int   g_part[512];
__device__ int   g_csr[EE];
__device__ float g_dinv_s[NN];
__device__ float g_dinv_n[NN];
__device__ float g_t0[(size_t)NN * D];
__device__ float g_h1[(size_t)NN * D];
__device__ float g_t1[(size_t)NN * D];
__device__ float g_h2[(size_t)NN * D];
__device__ float g_ur[(size_t)NN * D2];
__device__ float g_sum[D];
__device__ float g_sumsq[D];
__device__ float g_Wf[D * D2];
__device__ float g_bf[D2];
__device__ float g_pool[NG * D];
__device__ float g_m1[NG * 200];
__device__ float g_m2[NG * 300];
__device__ float g_m3[NG * 200];

// ---------------- small helper kernels ----------------
__global__ void zero_kernel() {
    int i = blockIdx.x * blockDim.x + threadIdx.x;
    int stride = gridDim.x * blockDim.x;
    for (int k = i; k < NN; k += stride) { g_deg[k] = 0; g_cursor[k] = 0; }
    for (int k = i; k < NG * D; k += stride) g_pool[k] = 0.f;
    if (i < D) { g_sum[i] = 0.f; g_sumsq[i] = 0.f; }
}

__global__ void deg_kernel(const int* __restrict__ dst) {
    int e = blockIdx.x * blockDim.x + threadIdx.x;
    if (e < EE) atomicAdd(&g_deg[dst[e]], 1);
}

// two-level exclusive scan of g_deg into g_off
__global__ void scan1_kernel() {
    __shared__ int sh[256];
    int tid = threadIdx.x;
    int i = blockIdx.x * 256 + tid;
    int v = (i < NN) ? g_deg[i] : 0;
    sh[tid] = v;
    __syncthreads();
    for (int ofs = 1; ofs < 256; ofs <<= 1) {
        int t = (tid >= ofs) ? sh[tid - ofs] : 0;
        __syncthreads();
        sh[tid] += t;
        __syncthreads();
    }
    if (i < NN) g_off[i] = sh[tid] - v;
    if (tid == 255) g_part[blockIdx.x] = sh[255];
}

__global__ void scan2_kernel() {
    __shared__ int sh[512];
    int tid = threadIdx.x;
    int v = (tid < SCAN_B) ? g_part[tid] : 0;
    sh[tid] = v;
    __syncthreads();
    for (int ofs = 1; ofs < 512; ofs <<= 1) {
        int t = (tid >= ofs) ? sh[tid - ofs] : 0;
        __syncthreads();
        sh[tid] += t;
        __syncthreads();
    }
    g_part[tid] = sh[tid] - v;
}

// scan finalize + dinv computation (fused)
__global__ void scan3_kernel() {
    int i = blockIdx.x * blockDim.x + threadIdx.x;
    if (i < NN) {
        g_off[i] += g_part[i >> 8];
        int d = g_deg[i];
        g_dinv_s[i] = rsqrtf((float)(d + 1));
        g_dinv_n[i] = (d > 0) ? rsqrtf((float)d) : 0.f;
    }
}

__global__ void csrfill_kernel(const int* __restrict__ src, const int* __restrict__ dst) {
    int e = blockIdx.x * blockDim.x + threadIdx.x;
    if (e < EE) {
        int d = dst[e];
        int pos = g_off[d] + atomicAdd(&g_cursor[d], 1);
        g_csr[pos] = src[e];
    }
}

// ---------------- node-level GEMM:  C[n x NC] = A[n x K] @ W[K x NC] (+bias) ----------------
// K-chunked; X tile stored transposed in smem for broadcast float4 loads.
// RPT rows per thread; 256 threads as 16x16; tile = 16*RPT rows x NC cols.
template <int K, int KC, int NC, int RPT>
__global__ void gemm_nodes(const float* __restrict__ A, const float* __restrict__ W,
                           const float* __restrict__ bias, float* __restrict__ C) {
    constexpr int ROWS = 16 * RPT;
    constexpr int CT = (NC + 15) / 16;
    constexpr int CTP = CT * 16;
    constexpr int XP = ROWS + 4;           // multiple of 4 -> float4-aligned rows
    __shared__ float Ws[KC * CTP];
    __shared__ float Xs[KC * XP];
    int tid = threadIdx.x;
    int rowbase = blockIdx.x * ROWS;
    int tx = tid & 15, ty = tid >> 4;

    float acc[RPT][CT];
#pragma unroll
    for (int i = 0; i < RPT; i++)
#pragma unroll
        for (int j = 0; j < CT; j++) acc[i][j] = 0.f;

    for (int k0 = 0; k0 < K; k0 += KC) {
        for (int idx = tid; idx < KC * CTP; idx += 256) {
            int k = idx / CTP, c = idx % CTP;
            Ws[idx] = (c < NC) ? W[(k0 + k) * NC + c] : 0.f;
        }
        for (int idx = tid; idx < ROWS * KC; idx += 256) {
            int r = idx / KC, k = idx % KC;
            int gr = rowbase + r;
            Xs[k * XP + r] = (gr < NN) ? A[(size_t)gr * K + k0 + k] : 0.f;
        }
        __syncthreads();

#pragma unroll 4
        for (int k = 0; k < KC; k++) {
            float x[RPT];
            const float4 xa = *(const float4*)&Xs[k * XP + ty * RPT];
            x[0] = xa.x; x[1] = xa.y; x[2] = xa.z; x[3] = xa.w;
            if (RPT == 8) {
                const float4 xb = *(const float4*)&Xs[k * XP + ty * RPT + 4];
                x[4] = xb.x; x[5] = xb.y; x[6] = xb.z; x[7] = xb.w;
            }
#pragma unroll
            for (int j = 0; j < CT; j++) {
                float w = Ws[k * CTP + tx + j * 16];
#pragma unroll
                for (int i = 0; i < RPT; i++) acc[i][j] = fmaf(x[i], w, acc[i][j]);
            }
        }
        __syncthreads();
    }

#pragma unroll
    for (int i = 0; i < RPT; i++) {
        int gr = rowbase + ty * RPT + i;
        if (gr >= NN) continue;
#pragma unroll
        for (int j = 0; j < CT; j++) {
            int c = tx + j * 16;
            if (c < NC) {
                float v = acc[i][j];
                if (bias) v += bias[c];
                C[(size_t)gr * NC + c] = v;
            }
        }
    }
}

// ---------------- GCN propagation with self loops: warp/node, float4, shfl indices ----------------
__global__ void prop_self_kernel(const float* __restrict__ T, const float* __restrict__ bias,
                                 float* __restrict__ out) {
    int node = blockIdx.x * 8 + (threadIdx.x >> 5);
    if (node >= NN) return;
    int lane = threadIdx.x & 31;
    int start = g_off[node];
    int cnt = g_deg[node];
    float di = g_dinv_s[node];
    bool act = lane < 25;
    int col = lane * 4;
    float4 a = make_float4(0.f, 0.f, 0.f, 0.f);

    for (int b = 0; b < cnt; b += 32) {
        int m = min(32, cnt - b);
        int jr = 0; float wr = 0.f;
        if (lane < m) { jr = g_csr[start + b + lane]; wr = g_dinv_s[jr]; }
        for (int e = 0; e < m; e++) {
            int j  = __shfl_sync(0xffffffffu, jr, e);
            float w = __shfl_sync(0xffffffffu, wr, e);
            if (act) {
                const float4 v = *(const float4*)(T + (size_t)j * D + col);
                a.x = fmaf(w, v.x, a.x); a.y = fmaf(w, v.y, a.y);
                a.z = fmaf(w, v.z, a.z); a.w = fmaf(w, v.w, a.w);
            }
        }
    }
    if (act) {
        const float4 v = *(const float4*)(T + (size_t)node * D + col);
        a.x = fmaf(di, v.x, a.x); a.y = fmaf(di, v.y, a.y);
        a.z = fmaf(di, v.z, a.z); a.w = fmaf(di, v.w, a.w);
        const float4 bb = *(const float4*)(bias + col);
        float4 o;
        o.x = fmaxf(fmaf(di, a.x, bb.x), 0.f);
        o.y = fmaxf(fmaf(di, a.y, bb.y), 0.f);
        o.z = fmaxf(fmaf(di, a.z, bb.z), 0.f);
        o.w = fmaxf(fmaf(di, a.w, bb.w), 0.f);
        *(float4*)(out + (size_t)node * D + col) = o;
    }
}

// ---------------- BatchNorm stats: register-column reduction, 1 atomic/block/col ----------------
__global__ void bn_stats_kernel() {
    int c = threadIdx.x;           // 128 threads, first 100 active
    if (c >= D) return;
    int r0 = blockIdx.x * 256;
    int r1 = min(r0 + 256, NN);
    float s = 0.f, q = 0.f;
    for (int r = r0; r < r1; r++) {
        float v = g_h2[(size_t)r * D + c];
        s += v;
        q = fmaf(v, v, q);
    }
    atomicAdd(&g_sum[c], s);
    atomicAdd(&g_sumsq[c], q);
}

// ---------------- fold BatchNorm affine into ARMA weights ----------------
// h = h2*s + t  =>  h@Wa = h2@(diag(s)Wa) + t@Wa
__global__ void fold_kernel(const float* __restrict__ gamma, const float* __restrict__ beta,
                            const float* __restrict__ Wa_init, const float* __restrict__ Wa_root,
                            const float* __restrict__ ba) {
    __shared__ float s[D], t[D];
    int tid = threadIdx.x;
    if (tid < D) {
        float mu = g_sum[tid] * (1.f / NN);
        float var = g_sumsq[tid] * (1.f / NN) - mu * mu;
        float rs = rsqrtf(var + 1e-5f);
        float sv = gamma[tid] * rs;
        s[tid] = sv;
        t[tid] = beta[tid] - mu * sv;
    }
    __syncthreads();
    for (int idx = tid; idx < D * D2; idx += blockDim.x) {
        int k = idx / D2, c = idx % D2;
        float w = (c < D) ? Wa_init[k * D + c] : Wa_root[k * D + (c - D)];
        g_Wf[idx] = s[k] * w;
    }
    for (int c = tid; c < D2; c += blockDim.x) {
        float acc;
        if (c < D) {
            acc = 0.f;
            for (int k = 0; k < D; k++) acc = fmaf(t[k], Wa_init[k * D + c], acc);
        } else {
            int cc = c - D;
            acc = ba[cc];
            for (int k = 0; k < D; k++) acc = fmaf(t[k], Wa_root[k * D + cc], acc);
        }
        g_bf[c] = acc;
    }
}

// ---------------- ARMA prop (no self loops) + root add + relu + pooled scatter ----------------
__global__ void arma_pool_kernel(const int* __restrict__ batch) {
    int node = blockIdx.x * 8 + (threadIdx.x >> 5);
    if (node >= NN) return;
    int lane = threadIdx.x & 31;
    int start = g_off[node];
    int cnt = g_deg[node];
    float di = g_dinv_n[node];
    bool act = lane < 25;
    int col = lane * 4;
    float4 a = make_float4(0.f, 0.f, 0.f, 0.f);

    for (int b = 0; b < cnt; b += 32) {
        int m = min(32, cnt - b);
        int jr = 0; float wr = 0.f;
        if (lane < m) { jr = g_csr[start + b + lane]; wr = g_dinv_n[jr]; }
        for (int e = 0; e < m; e++) {
            int j  = __shfl_sync(0xffffffffu, jr, e);
            float w = __shfl_sync(0xffffffffu, wr, e);
            if (act) {
                const float4 v = *(const float4*)(g_ur + (size_t)j * D2 + col);
                a.x = fmaf(w, v.x, a.x); a.y = fmaf(w, v.y, a.y);
                a.z = fmaf(w, v.z, a.z); a.w = fmaf(w, v.w, a.w);
            }
        }
    }
    if (act) {
        const float4 r = *(const float4*)(g_ur + (size_t)node * D2 + D + col);
        float v0 = fmaxf(fmaf(di, a.x, r.x), 0.f);
        float v1 = fmaxf(fmaf(di, a.y, r.y), 0.f);
        float v2 = fmaxf(fmaf(di, a.z, r.z), 0.f);
        float v3 = fmaxf(fmaf(di, a.w, r.w), 0.f);
        float* p = g_pool + (size_t)batch[node] * D + col;
        atomicAdd(&p[0], v0);
        atomicAdd(&p[1], v1);
        atomicAdd(&p[2], v2);
        atomicAdd(&p[3], v3);
    }
}

// ---------------- small MLP GEMM (row per block) ----------------
template <int K, int NC, bool RELU>
__global__ void mlp_gemm(const float* __restrict__ A, const float* __restrict__ W,
                         const float* __restrict__ b, float* __restrict__ C) {
    __shared__ float As[K];
    int r = blockIdx.x;
    for (int k = threadIdx.x; k < K; k += blockDim.x) As[k] = A[r * K + k];
    __syncthreads();
    for (int c = threadIdx.x; c < NC; c += blockDim.x) {
        float acc = b[c];
#pragma unroll 4
        for (int k = 0; k < K; k++) acc = fmaf(As[k], W[k * NC + c], acc);
        C[r * NC + c] = RELU ? fmaxf(acc, 0.f) : acc;
    }
}

// ---------------- host helper: real device address of a __device__ symbol ----------------
static float* symaddr(const void* sym) {
    void* p = nullptr;
    cudaGetSymbolAddress(&p, sym);
    return (float*)p;
}

// ---------------- launcher ----------------
extern "C" void kernel_launch(void* const* d_in, const int* in_sizes, int n_in,
                              void* d_out, int out_size) {
    const float* x       = (const float*)d_in[0];
    const int*   src     = (const int*)d_in[1];
    const int*   dst     = (const int*)d_in[2];
    const int*   batch   = (const int*)d_in[3];
    const float* W1      = (const float*)d_in[4];
    const float* b1      = (const float*)d_in[5];
    const float* W2      = (const float*)d_in[6];
    const float* b2      = (const float*)d_in[7];
    const float* gamma   = (const float*)d_in[8];
    const float* beta    = (const float*)d_in[9];
    const float* Wa_init = (const float*)d_in[10];
    const float* Wa_root = (const float*)d_in[11];
    const float* ba      = (const float*)d_in[12];
    const float* Wf1     = (const float*)d_in[13];
    const float* bf1     = (const float*)d_in[14];
    const float* Wf2     = (const float*)d_in[15];
    const float* bf2     = (const float*)d_in[16];
    const float* Wf3     = (const float*)d_in[17];
    const float* bf3     = (const float*)d_in[18];
    const float* Wf4     = (const float*)d_in[19];
    const float* bf4     = (const float*)d_in[20];
    float* out = (float*)d_out;

    // real device addresses of the scratch buffers (NOT the host shadows!)
    float* p_t0   = symaddr(g_t0);
    float* p_h1   = symaddr(g_h1);
    float* p_t1   = symaddr(g_t1);
    float* p_h2   = symaddr(g_h2);
    float* p_ur   = symaddr(g_ur);
    float* p_Wf   = symaddr(g_Wf);
    float* p_bf   = symaddr(g_bf);
    float* p_pool = symaddr(g_pool);
    float* p_m1   = symaddr(g_m1);
    float* p_m2   = symaddr(g_m2);
    float* p_m3   = symaddr(g_m3);

    const int GB_N = (NN + 255) / 256;       // 391
    const int GB_E = (EE + 255) / 256;       // 6250
    const int GB_P = (NN + 7) / 8;           // 12500 (warp per node, 8/block)

    zero_kernel<<<GB_N, 256>>>();
    deg_kernel<<<GB_E, 256>>>(dst);
    scan1_kernel<<<SCAN_B, 256>>>();
    scan2_kernel<<<1, 512>>>();
    scan3_kernel<<<GB_N, 256>>>();
    csrfill_kernel<<<GB_E, 256>>>(src, dst);

    // SGConv 1: t0 = x @ W1 ; h1 = relu(prop_self(t0) + b1)
    gemm_nodes<K1, 32, D, 8><<<(NN + 127) / 128, 256>>>(x, W1, nullptr, p_t0);
    prop_self_kernel<<<GB_P, 256>>>(p_t0, b1, p_h1);

    // SGConv 2: t1 = h1 @ W2 ; h2 = relu(prop_self(t1) + b2)
    gemm_nodes<D, 25, D, 8><<<(NN + 127) / 128, 256>>>(p_h1, W2, nullptr, p_t1);
    prop_self_kernel<<<GB_P, 256>>>(p_t1, b2, p_h2);

    // BatchNorm stats + fold into ARMA weights
    bn_stats_kernel<<<GB_N, 128>>>();
    fold_kernel<<<1, 256>>>(gamma, beta, Wa_init, Wa_root, ba);

    // ARMA: ur = h2 @ Wf + bf  (u = cols 0..99, r = cols 100..199)
    gemm_nodes<D, 25, D2, 4><<<(NN + 63) / 64, 256>>>(p_h2, p_Wf, p_bf, p_ur);

    // a = relu(prop_noself(u) + r), pooled by graph id (fused)
    arma_pool_kernel<<<GB_P, 256>>>(batch);

    // MLP head on [512, 100]
    mlp_gemm<100, 200, true><<<NG, 256>>>(p_pool, Wf1, bf1, p_m1);
    mlp_gemm<200, 300, true><<<NG, 256>>>(p_m1, Wf2, bf2, p_m2);
    mlp_gemm<300, 200, true><<<NG, 256>>>(p_m2, Wf3, bf3, p_m3);
    mlp_gemm<200, 1, false><<<NG, 32>>>(p_m3, Wf4, bf4, out);
}